// round 13
// baseline (speedup 1.0000x reference)
#include <cuda_runtime.h>
#include <math.h>

#define HW 1024

// ---------------- scratch ----------------
// layout (float offsets):
// Sh: 4 * 131072      (state h per stream,layer: [2 batch][64][1024])
// Sc: 4 * 131072
// G : 2 * 524288      (gates per stream: [2 batch][256][1024])
// HA/CA/HB/CB: each 2 * 131072
// Q/K/V: each 8 * 65536
// DEC: 4 * 65536
__device__ float SCRATCH[4980736];

// ---------------- arg structs ----------------
struct ConvArgs {
  const float* x[4]; const float* h[4];
  const float* w[4]; const float* b[4];
  float* out[4];
  int cx, chh, cout, relu;
};
struct LstmArgs {
  const float* g[4]; const float* cold[4];
  float* hn[4]; float* cn[4];
};
struct QKVArgs {
  const float* xq[8]; const float* xkv[8];
  const float* w[8];  const float* b[8];
  float* q[8]; float* k[8]; float* v[8];
};
struct FlashArgs {
  const float* q[8]; const float* k[8]; const float* v[8];
  const float* xq[8]; float* out[8];
};

// ---------------- zero ----------------
__global__ void zero_kernel(float* p, int n) {
  int i = blockIdx.x * 256 + threadIdx.x;
  if (i < n) p[i] = 0.f;
}

// ---------------- 3x3 conv (SAME, stride 1), 8 out-ch per block ----------------
__global__ __launch_bounds__(256) void conv3x3_kernel(ConvArgs A) {
  int u  = blockIdx.y;
  int ob = blockIdx.x * 8;
  int t  = threadIdx.x;
  int tx = t & 31, ty = t >> 5;
  __shared__ float plane[34 * 36];
  __shared__ float wsm[8 * 9];
  for (int i = t; i < 34 * 36; i += 256) plane[i] = 0.f;  // border stays 0 (SAME pad)
  int ctot = A.cx + A.chh;
  int nco = A.cout - ob; if (nco > 8) nco = 8;
  float acc[8][4];
  #pragma unroll
  for (int j = 0; j < 8; j++)
    #pragma unroll
    for (int k = 0; k < 4; k++) acc[j][k] = 0.f;
  const float* xp = A.x[u];
  const float* hp = A.h[u];
  const float* wp = A.w[u];
  __syncthreads();
  for (int ci = 0; ci < ctot; ci++) {
    const float* src = (ci < A.cx) ? (xp + ci * HW) : (hp + (ci - A.cx) * HW);
    #pragma unroll
    for (int k = 0; k < 4; k++) {
      int idx = t + k * 256;
      int y = idx >> 5, xx = idx & 31;
      plane[(y + 1) * 36 + (xx + 1)] = src[idx];
    }
    if (t < 72) {
      int j = t / 9, t9 = t % 9;
      wsm[t] = (j < nco) ? wp[(ob + j) * ctot * 9 + ci * 9 + t9] : 0.f;
    }
    __syncthreads();
    #pragma unroll
    for (int k = 0; k < 4; k++) {
      int y = ty + k * 8;
      float pv[9];
      #pragma unroll
      for (int dy = 0; dy < 3; dy++)
        #pragma unroll
        for (int dx = 0; dx < 3; dx++)
          pv[dy * 3 + dx] = plane[(y + dy) * 36 + tx + dx];
      #pragma unroll
      for (int j = 0; j < 8; j++) {
        float a = acc[j][k];
        #pragma unroll
        for (int q = 0; q < 9; q++) a += wsm[j * 9 + q] * pv[q];
        acc[j][k] = a;
      }
    }
    __syncthreads();
  }
  float* op = A.out[u];
  const float* bp = A.b[u];
  for (int j = 0; j < nco; j++) {
    float bias = bp[ob + j];
    #pragma unroll
    for (int k = 0; k < 4; k++) {
      float v = acc[j][k] + bias;
      if (A.relu) v = fmaxf(v, 0.f);
      op[(ob + j) * HW + (ty + k * 8) * 32 + tx] = v;
    }
  }
}

// ---------------- LSTM pointwise ----------------
__global__ __launch_bounds__(256) void lstm_kernel(LstmArgs A) {
  int u = blockIdx.y;
  int e = blockIdx.x * 256 + threadIdx.x;   // 0..65535
  int ch = e >> 10, hw = e & 1023;
  const float* g = A.g[u];
  float gi = g[ch * HW + hw];
  float gf = g[(64 + ch) * HW + hw];
  float go = g[(128 + ch) * HW + hw];
  float gg = g[(192 + ch) * HW + hw];
  float i = 1.f / (1.f + __expf(-gi));
  float f = 1.f / (1.f + __expf(-gf));
  float o = 1.f / (1.f + __expf(-go));
  float gt = tanhf(gg);
  float c = f * A.cold[u][e] + i * gt;
  A.cn[u][e] = c;
  A.hn[u][e] = o * tanhf(c);
}

// ---------------- QKV 1x1 projections (64x64 GEMM over 1024 tokens) ----------------
// grid: (4 hw-tiles of 256, 6 = {q,k,v} x {half}, 8 units), block 128
__global__ __launch_bounds__(128) void qkv_kernel(QKVArgs A) {
  int u = blockIdx.z;
  int s  = blockIdx.y >> 1;   // 0=q 1=k 2=v
  int oh = blockIdx.y & 1;    // output-channel half
  int hw0 = blockIdx.x * 256 + threadIdx.x;
  __shared__ float wsm[32 * 64];
  __shared__ float bsm[32];
  const float* wp = A.w[u] + s * 4096 + oh * 32 * 64;
  for (int i = threadIdx.x; i < 2048; i += 128) wsm[i] = wp[i];
  if (threadIdx.x < 32) bsm[threadIdx.x] = A.b[u][s * 64 + oh * 32 + threadIdx.x];
  const float* x = (s == 0) ? A.xq[u] : A.xkv[u];
  __syncthreads();
  float a0[32], a1[32];
  #pragma unroll
  for (int o = 0; o < 32; o++) { a0[o] = bsm[o]; a1[o] = bsm[o]; }
  #pragma unroll 4
  for (int c = 0; c < 64; c++) {
    float x0 = x[c * HW + hw0];
    float x1 = x[c * HW + hw0 + 128];
    #pragma unroll
    for (int o = 0; o < 32; o++) {
      float w = wsm[o * 64 + c];
      a0[o] += w * x0; a1[o] += w * x1;
    }
  }
  float* out = (s == 0) ? A.q[u] : ((s == 1) ? A.k[u] : A.v[u]);
  #pragma unroll
  for (int o = 0; o < 32; o++) {
    out[(oh * 32 + o) * HW + hw0]       = a0[o];
    out[(oh * 32 + o) * HW + hw0 + 128] = a1[o];
  }
}

// ---------------- flash attention (64 q-rows/block, 64-m tiles, online softmax) ----------------
// grid (16 n-tiles, 8 units), block 256, dynamic smem 50688 B
__global__ __launch_bounds__(256) void flash_kernel(FlashArgs A) {
  extern __shared__ float sm[];
  float* q_s  = sm;                // [n][c] stride 65
  float* kp_s = sm + 64 * 65;      // k: [c][m] stride 65 ; then p: [n][m]
  float* v_s  = sm + 2 * 64 * 65;  // [m][c] stride 65
  float* row_max  = sm + 3 * 64 * 65;
  float* row_sum  = row_max + 64;
  float* row_corr = row_sum + 64;
  int u  = blockIdx.y;
  int n0 = blockIdx.x * 64;
  int t  = threadIdx.x;
  int tn = t >> 4, tm = t & 15;
  const float* qg = A.q[u];
  const float* kg = A.k[u];
  const float* vg = A.v[u];
  #pragma unroll
  for (int i = 0; i < 16; i++) {
    int e = t + i * 256;
    int n = e & 63, c = e >> 6;
    q_s[n * 65 + c] = qg[c * HW + n0 + n] * 0.125f;  // fold 1/sqrt(64)
  }
  if (t < 64) { row_max[t] = -3.0e38f; row_sum[t] = 0.f; }
  float o_acc[4][4];
  #pragma unroll
  for (int i = 0; i < 4; i++)
    #pragma unroll
    for (int j = 0; j < 4; j++) o_acc[i][j] = 0.f;
  __syncthreads();

  for (int mt = 0; mt < 16; mt++) {
    int m0 = mt * 64;
    #pragma unroll
    for (int i = 0; i < 16; i++) {
      int e = t + i * 256;
      int m = e & 63, c = e >> 6;
      kp_s[c * 65 + m] = kg[c * HW + m0 + m];
      v_s [m * 65 + c] = vg[c * HW + m0 + m];
    }
    __syncthreads();
    // ---- S tile (4x4 per thread) ----
    float s[4][4];
    #pragma unroll
    for (int i = 0; i < 4; i++)
      #pragma unroll
      for (int j = 0; j < 4; j++) s[i][j] = 0.f;
    #pragma unroll 8
    for (int c = 0; c < 64; c++) {
      float qv[4], kv[4];
      #pragma unroll
      for (int i = 0; i < 4; i++) qv[i] = q_s[(tn * 4 + i) * 65 + c];
      #pragma unroll
      for (int j = 0; j < 4; j++) kv[j] = kp_s[c * 65 + tm * 4 + j];
      #pragma unroll
      for (int i = 0; i < 4; i++)
        #pragma unroll
        for (int j = 0; j < 4; j++) s[i][j] += qv[i] * kv[j];
    }
    // ---- per-row tile max (reduce over 16 tm lanes) ----
    float tmax[4];
    #pragma unroll
    for (int i = 0; i < 4; i++) {
      float m_ = fmaxf(fmaxf(s[i][0], s[i][1]), fmaxf(s[i][2], s[i][3]));
      #pragma unroll
      for (int ofs = 8; ofs >= 1; ofs >>= 1)
        m_ = fmaxf(m_, __shfl_xor_sync(0xffffffffu, m_, ofs));
      tmax[i] = m_;
    }
    if (tm == 0) {
      #pragma unroll
      for (int i = 0; i < 4; i++) {
        int n = tn * 4 + i;
        float old = row_max[n];
        float nm = fmaxf(old, tmax[i]);
        float corr = __expf(old - nm);
        row_max[n] = nm;
        row_corr[n] = corr;
        row_sum[n] *= corr;
      }
    }
    __syncthreads();   // S-phase reads of kp_s done; row stats visible
    // ---- P = exp(S - max), stash in kp_s as [n][m]; accumulate row sums ----
    #pragma unroll
    for (int i = 0; i < 4; i++) {
      int n = tn * 4 + i;
      float nm = row_max[n];
      float psum = 0.f;
      #pragma unroll
      for (int j = 0; j < 4; j++) {
        float p = __expf(s[i][j] - nm);
        kp_s[n * 65 + tm * 4 + j] = p;
        psum += p;
      }
      #pragma unroll
      for (int ofs = 8; ofs >= 1; ofs >>= 1)
        psum += __shfl_xor_sync(0xffffffffu, psum, ofs);
      if (tm == 0) row_sum[n] += psum;
    }
    __syncthreads();   // p visible
    // ---- O rescale + AV (thread = 4 rows x 4 channels, c0 = tm*4) ----
    #pragma unroll
    for (int i = 0; i < 4; i++) {
      float corr = row_corr[tn * 4 + i];
      #pragma unroll
      for (int j = 0; j < 4; j++) o_acc[i][j] *= corr;
    }
    #pragma unroll 8
    for (int m = 0; m < 64; m++) {
      float pv[4], vv[4];
      #pragma unroll
      for (int i = 0; i < 4; i++) pv[i] = kp_s[(tn * 4 + i) * 65 + m];
      #pragma unroll
      for (int j = 0; j < 4; j++) vv[j] = v_s[m * 65 + tm * 4 + j];
      #pragma unroll
      for (int i = 0; i < 4; i++)
        #pragma unroll
        for (int j = 0; j < 4; j++) o_acc[i][j] += pv[i] * vv[j];
    }
    __syncthreads();   // before next tile overwrites kp_s / v_s
  }
  const float* xqg = A.xq[u];
  float* og = A.out[u];
  #pragma unroll
  for (int i = 0; i < 4; i++) {
    int n = n0 + tn * 4 + i;
    float inv = 1.f / row_sum[tn * 4 + i];
    #pragma unroll
    for (int j = 0; j < 4; j++) {
      int c = tm * 4 + j;
      og[c * HW + n] = o_acc[i][j] * inv + xqg[c * HW + n];
    }
  }
}

// ---------------- host orchestration ----------------
extern "C" void kernel_launch(void* const* d_in, const int* in_sizes, int n_in,
                              void* d_out, int out_size) {
  const float* x1_seq = (const float*)d_in[0];
  const float* x2_seq = (const float*)d_in[1];
  const float* cw[2][2]; const float* cb[2][2];
  cw[0][0] = (const float*)d_in[2]; cb[0][0] = (const float*)d_in[3];
  cw[0][1] = (const float*)d_in[4]; cb[0][1] = (const float*)d_in[5];
  cw[1][0] = (const float*)d_in[6]; cb[1][0] = (const float*)d_in[7];
  cw[1][1] = (const float*)d_in[8]; cb[1][1] = (const float*)d_in[9];
  const float* sah_w = (const float*)d_in[10]; const float* sah_b = (const float*)d_in[11];
  const float* sac_w = (const float*)d_in[12]; const float* sac_b = (const float*)d_in[13];
  const float* cah_w = (const float*)d_in[14]; const float* cah_b = (const float*)d_in[15];
  const float* cac_w = (const float*)d_in[16]; const float* cac_b = (const float*)d_in[17];
  const float* dec_w1 = (const float*)d_in[18]; const float* dec_b1 = (const float*)d_in[19];
  const float* dec_w2 = (const float*)d_in[20]; const float* dec_b2 = (const float*)d_in[21];
  float* out = (float*)d_out;

  float* base = nullptr;
  cudaGetSymbolAddress((void**)&base, SCRATCH);

  const int SZ_SL = 131072;  // [2 batch][64][1024]
  float* Sh  = base;                 // 4*SZ_SL
  float* Sc  = base + 4 * SZ_SL;     // 4*SZ_SL
  float* G   = base + 8 * SZ_SL;     // 2*524288
  float* HA  = G  + 2 * 524288;
  float* CA  = HA + 262144;
  float* HB  = CA + 262144;
  float* CB  = HB + 262144;
  float* Qb  = CB + 262144;          // 8*65536
  float* Kb  = Qb + 524288;
  float* Vb  = Kb + 524288;
  float* DEC = Vb + 524288;          // 4*65536

  cudaFuncSetAttribute(flash_kernel, cudaFuncAttributeMaxDynamicSharedMemorySize, 50688);

  // zero initial state (Sh + Sc)
  zero_kernel<<<(8 * SZ_SL + 255) / 256, 256>>>(base, 8 * SZ_SL);

  auto Shp = [&](int s, int l) { return Sh + (s * 2 + l) * SZ_SL; };
  auto Scp = [&](int s, int l) { return Sc + (s * 2 + l) * SZ_SL; };

  auto step = [&](const float* x1b0, const float* x1b1,
                  const float* x2b0, const float* x2b1) {
    const float* xin[2][2] = {{x1b0, x1b1}, {x2b0, x2b1}};
    for (int l = 0; l < 2; l++) {
      int cx = (l == 0) ? 1 : 64;
      // gate conv (4 units: stream x batch)
      ConvArgs ca;
      for (int u = 0; u < 4; u++) {
        int s = u >> 1, b = u & 1;
        ca.x[u] = (l == 0) ? xin[s][b] : (Shp(s, 0) + b * 65536);
        ca.h[u] = Shp(s, l) + b * 65536;
        ca.w[u] = cw[s][l]; ca.b[u] = cb[s][l];
        ca.out[u] = G + s * 524288 + b * 262144;
      }
      ca.cx = cx; ca.chh = 64; ca.cout = 256; ca.relu = 0;
      conv3x3_kernel<<<dim3(32, 4), 256>>>(ca);
      // LSTM pointwise
      LstmArgs la;
      for (int u = 0; u < 4; u++) {
        int s = u >> 1, b = u & 1;
        la.g[u]    = G + s * 524288 + b * 262144;
        la.cold[u] = Scp(s, l) + b * 65536;
        la.hn[u]   = HA + s * 131072 + b * 65536;
        la.cn[u]   = CA + s * 131072 + b * 65536;
      }
      lstm_kernel<<<dim3(256, 4), 256>>>(la);
      // ---- self attention group (8 units) ----
      QKVArgs qa; FlashArgs fa;
      for (int a = 0; a < 4; a++) {
        int s = a >> 1; int isC = a & 1;
        const float* src = (isC ? CA : HA) + s * 131072;
        float* dst       = (isC ? CB : HB) + s * 131072;
        const float* w  = isC ? (sac_w + l * 12288) : (sah_w + l * 12288);
        const float* bb = isC ? (sac_b + l * 192)   : (sah_b + l * 192);
        for (int b = 0; b < 2; b++) {
          int uu = a * 2 + b;
          qa.xq[uu] = src + b * 65536; qa.xkv[uu] = src + b * 65536;
          qa.w[uu] = w; qa.b[uu] = bb;
          qa.q[uu] = Qb + uu * 65536; qa.k[uu] = Kb + uu * 65536; qa.v[uu] = Vb + uu * 65536;
          fa.q[uu] = qa.q[uu]; fa.k[uu] = qa.k[uu]; fa.v[uu] = qa.v[uu];
          fa.xq[uu] = src + b * 65536; fa.out[uu] = dst + b * 65536;
        }
      }
      qkv_kernel<<<dim3(4, 6, 8), 128>>>(qa);
      flash_kernel<<<dim3(16, 8), 256, 50688>>>(fa);
      // ---- cross attention group (8 units) ----
      for (int a = 0; a < 4; a++) {
        int s = a >> 1; int isC = a & 1;
        int so = 1 - s;
        const float* srcq = (isC ? CB : HB) + s  * 131072;
        const float* srck = (isC ? CB : HB) + so * 131072;
        float* dst = isC ? Scp(s, l) : Shp(s, l);
        const float* w  = isC ? (cac_w + l * 12288) : (cah_w + l * 12288);
        const float* bb = isC ? (cac_b + l * 192)   : (cah_b + l * 192);
        for (int b = 0; b < 2; b++) {
          int uu = a * 2 + b;
          qa.xq[uu] = srcq + b * 65536; qa.xkv[uu] = srck + b * 65536;
          qa.w[uu] = w; qa.b[uu] = bb;
          fa.xq[uu] = srcq + b * 65536; fa.out[uu] = dst + b * 65536;
        }
      }
      qkv_kernel<<<dim3(4, 6, 8), 128>>>(qa);
      flash_kernel<<<dim3(16, 8), 256, 50688>>>(fa);
    }
  };

  auto decode = [&](float* o1b0, float* o1b1, float* o2b0, float* o2b1) {
    ConvArgs c1;
    for (int u = 0; u < 4; u++) {
      int s = u >> 1, b = u & 1;
      c1.x[u] = Shp(s, 1) + b * 65536;
      c1.h[u] = nullptr;
      c1.w[u] = dec_w1; c1.b[u] = dec_b1;
      c1.out[u] = DEC + u * 65536;
    }
    c1.cx = 64; c1.chh = 0; c1.cout = 64; c1.relu = 1;
    conv3x3_kernel<<<dim3(8, 4), 256>>>(c1);
    ConvArgs c2;
    float* outs[4] = {o1b0, o1b1, o2b0, o2b1};
    for (int u = 0; u < 4; u++) {
      c2.x[u] = DEC + u * 65536;
      c2.h[u] = nullptr;
      c2.w[u] = dec_w2; c2.b[u] = dec_b2;
      c2.out[u] = outs[u];
    }
    c2.cx = 64; c2.chh = 0; c2.cout = 1; c2.relu = 0;
    conv3x3_kernel<<<dim3(1, 4), 256>>>(c2);
  };

  // output offsets (floats):
  // preds1: 0       [2][4][1024]
  // preds2: 8192    [2][4][1024]
  // warm1:  16384   [2][2][1024]
  // warm2:  20480   [2][2][1024]

  // warm steps
  for (int tt = 0; tt < 3; tt++) {
    const float* x1b0 = x1_seq + (0 * 3 + tt) * 1024;
    const float* x1b1 = x1_seq + (1 * 3 + tt) * 1024;
    const float* x2b0 = x2_seq + (0 * 3 + tt) * 1024;
    const float* x2b1 = x2_seq + (1 * 3 + tt) * 1024;
    step(x1b0, x1b1, x2b0, x2b1);
    if (tt < 2) {
      decode(out + 16384 + 0 * 2048 + tt * 1024,
             out + 16384 + 1 * 2048 + tt * 1024,
             out + 20480 + 0 * 2048 + tt * 1024,
             out + 20480 + 1 * 2048 + tt * 1024);
    }
  }
  // future steps (future_steps = 4 fixed by setup_inputs; last step's state unused -> skipped)
  for (int i = 0; i < 4; i++) {
    float* p1b0 = out + 0 * 4096 + i * 1024;
    float* p1b1 = out + 1 * 4096 + i * 1024;
    float* p2b0 = out + 8192 + 0 * 4096 + i * 1024;
    float* p2b1 = out + 8192 + 1 * 4096 + i * 1024;
    decode(p1b0, p1b1, p2b0, p2b1);
    if (i < 3) step(p1b0, p1b1, p2b0, p2b1);
  }
}

// round 14
// speedup vs baseline: 1.0000x; 1.0000x over previous
#include <cuda_runtime.h>
#include <math.h>

#define HW 1024

// ---------------- scratch ----------------
// layout (float offsets):
// Sh: 4 * 131072      (state h per stream,layer: [2 batch][64][1024])
// Sc: 4 * 131072
// G : 2 * 524288      (gates per stream: [2 batch][256][1024])
// HA/CA/HB/CB: each 2 * 131072
// Q/K/V: each 8 * 65536
// DEC: 4 * 65536
__device__ float SCRATCH[4980736];

// ---------------- arg structs ----------------
struct ConvArgs {
  const float* x[4]; const float* h[4];
  const float* w[4]; const float* b[4];
  float* out[4];
  int cx, chh, cout, relu;
};
struct LstmArgs {
  const float* g[4]; const float* cold[4];
  float* hn[4]; float* cn[4];
};
struct QKVArgs {
  const float* xq[8]; const float* xkv[8];
  const float* w[8];  const float* b[8];
  float* q[8]; float* k[8]; float* v[8];
};
struct FlashArgs {
  const float* q[8]; const float* k[8]; const float* v[8];
  const float* xq[8]; float* out[8];
};

// ---------------- zero ----------------
__global__ void zero_kernel(float* p, int n) {
  int i = blockIdx.x * 256 + threadIdx.x;
  if (i < n) p[i] = 0.f;
}

// ---------------- 3x3 conv (SAME, stride 1), 8 out-ch per block ----------------
__global__ __launch_bounds__(256) void conv3x3_kernel(ConvArgs A) {
  int u  = blockIdx.y;
  int ob = blockIdx.x * 8;
  int t  = threadIdx.x;
  int tx = t & 31, ty = t >> 5;
  __shared__ float plane[34 * 36];
  __shared__ float wsm[8 * 9];
  for (int i = t; i < 34 * 36; i += 256) plane[i] = 0.f;  // border stays 0 (SAME pad)
  int ctot = A.cx + A.chh;
  int nco = A.cout - ob; if (nco > 8) nco = 8;
  float acc[8][4];
  #pragma unroll
  for (int j = 0; j < 8; j++)
    #pragma unroll
    for (int k = 0; k < 4; k++) acc[j][k] = 0.f;
  const float* xp = A.x[u];
  const float* hp = A.h[u];
  const float* wp = A.w[u];
  __syncthreads();
  for (int ci = 0; ci < ctot; ci++) {
    const float* src = (ci < A.cx) ? (xp + ci * HW) : (hp + (ci - A.cx) * HW);
    #pragma unroll
    for (int k = 0; k < 4; k++) {
      int idx = t + k * 256;
      int y = idx >> 5, xx = idx & 31;
      plane[(y + 1) * 36 + (xx + 1)] = src[idx];
    }
    if (t < 72) {
      int j = t / 9, t9 = t % 9;
      wsm[t] = (j < nco) ? wp[(ob + j) * ctot * 9 + ci * 9 + t9] : 0.f;
    }
    __syncthreads();
    #pragma unroll
    for (int k = 0; k < 4; k++) {
      int y = ty + k * 8;
      float pv[9];
      #pragma unroll
      for (int dy = 0; dy < 3; dy++)
        #pragma unroll
        for (int dx = 0; dx < 3; dx++)
          pv[dy * 3 + dx] = plane[(y + dy) * 36 + tx + dx];
      #pragma unroll
      for (int j = 0; j < 8; j++) {
        float a = acc[j][k];
        #pragma unroll
        for (int q = 0; q < 9; q++) a += wsm[j * 9 + q] * pv[q];
        acc[j][k] = a;
      }
    }
    __syncthreads();
  }
  float* op = A.out[u];
  const float* bp = A.b[u];
  for (int j = 0; j < nco; j++) {
    float bias = bp[ob + j];
    #pragma unroll
    for (int k = 0; k < 4; k++) {
      float v = acc[j][k] + bias;
      if (A.relu) v = fmaxf(v, 0.f);
      op[(ob + j) * HW + (ty + k * 8) * 32 + tx] = v;
    }
  }
}

// ---------------- LSTM pointwise ----------------
__global__ __launch_bounds__(256) void lstm_kernel(LstmArgs A) {
  int u = blockIdx.y;
  int e = blockIdx.x * 256 + threadIdx.x;   // 0..65535
  int ch = e >> 10, hw = e & 1023;
  const float* g = A.g[u];
  float gi = g[ch * HW + hw];
  float gf = g[(64 + ch) * HW + hw];
  float go = g[(128 + ch) * HW + hw];
  float gg = g[(192 + ch) * HW + hw];
  float i = 1.f / (1.f + __expf(-gi));
  float f = 1.f / (1.f + __expf(-gf));
  float o = 1.f / (1.f + __expf(-go));
  float gt = tanhf(gg);
  float c = f * A.cold[u][e] + i * gt;
  A.cn[u][e] = c;
  A.hn[u][e] = o * tanhf(c);
}

// ---------------- QKV 1x1 projections (64x64 GEMM over 1024 tokens) ----------------
// grid: (4 hw-tiles of 256, 6 = {q,k,v} x {half}, 8 units), block 128
__global__ __launch_bounds__(128) void qkv_kernel(QKVArgs A) {
  int u = blockIdx.z;
  int s  = blockIdx.y >> 1;   // 0=q 1=k 2=v
  int oh = blockIdx.y & 1;    // output-channel half
  int hw0 = blockIdx.x * 256 + threadIdx.x;
  __shared__ float wsm[32 * 64];
  __shared__ float bsm[32];
  const float* wp = A.w[u] + s * 4096 + oh * 32 * 64;
  for (int i = threadIdx.x; i < 2048; i += 128) wsm[i] = wp[i];
  if (threadIdx.x < 32) bsm[threadIdx.x] = A.b[u][s * 64 + oh * 32 + threadIdx.x];
  const float* x = (s == 0) ? A.xq[u] : A.xkv[u];
  __syncthreads();
  float a0[32], a1[32];
  #pragma unroll
  for (int o = 0; o < 32; o++) { a0[o] = bsm[o]; a1[o] = bsm[o]; }
  #pragma unroll 4
  for (int c = 0; c < 64; c++) {
    float x0 = x[c * HW + hw0];
    float x1 = x[c * HW + hw0 + 128];
    #pragma unroll
    for (int o = 0; o < 32; o++) {
      float w = wsm[o * 64 + c];
      a0[o] += w * x0; a1[o] += w * x1;
    }
  }
  float* out = (s == 0) ? A.q[u] : ((s == 1) ? A.k[u] : A.v[u]);
  #pragma unroll
  for (int o = 0; o < 32; o++) {
    out[(oh * 32 + o) * HW + hw0]       = a0[o];
    out[(oh * 32 + o) * HW + hw0 + 128] = a1[o];
  }
}

// ---------------- flash attention (64 q-rows/block, 64-m tiles, online softmax) ----------------
// grid (16 n-tiles, 8 units), block 256, dynamic smem 50688 B
__global__ __launch_bounds__(256) void flash_kernel(FlashArgs A) {
  extern __shared__ float sm[];
  float* q_s  = sm;                // [n][c] stride 65
  float* kp_s = sm + 64 * 65;      // k: [c][m] stride 65 ; then p: [n][m]
  float* v_s  = sm + 2 * 64 * 65;  // [m][c] stride 65
  float* row_max  = sm + 3 * 64 * 65;
  float* row_sum  = row_max + 64;
  float* row_corr = row_sum + 64;
  int u  = blockIdx.y;
  int n0 = blockIdx.x * 64;
  int t  = threadIdx.x;
  int tn = t >> 4, tm = t & 15;
  const float* qg = A.q[u];
  const float* kg = A.k[u];
  const float* vg = A.v[u];
  #pragma unroll
  for (int i = 0; i < 16; i++) {
    int e = t + i * 256;
    int n = e & 63, c = e >> 6;
    q_s[n * 65 + c] = qg[c * HW + n0 + n] * 0.125f;  // fold 1/sqrt(64)
  }
  if (t < 64) { row_max[t] = -3.0e38f; row_sum[t] = 0.f; }
  float o_acc[4][4];
  #pragma unroll
  for (int i = 0; i < 4; i++)
    #pragma unroll
    for (int j = 0; j < 4; j++) o_acc[i][j] = 0.f;
  __syncthreads();

  for (int mt = 0; mt < 16; mt++) {
    int m0 = mt * 64;
    #pragma unroll
    for (int i = 0; i < 16; i++) {
      int e = t + i * 256;
      int m = e & 63, c = e >> 6;
      kp_s[c * 65 + m] = kg[c * HW + m0 + m];
      v_s [m * 65 + c] = vg[c * HW + m0 + m];
    }
    __syncthreads();
    // ---- S tile (4x4 per thread) ----
    float s[4][4];
    #pragma unroll
    for (int i = 0; i < 4; i++)
      #pragma unroll
      for (int j = 0; j < 4; j++) s[i][j] = 0.f;
    #pragma unroll 8
    for (int c = 0; c < 64; c++) {
      float qv[4], kv[4];
      #pragma unroll
      for (int i = 0; i < 4; i++) qv[i] = q_s[(tn * 4 + i) * 65 + c];
      #pragma unroll
      for (int j = 0; j < 4; j++) kv[j] = kp_s[c * 65 + tm * 4 + j];
      #pragma unroll
      for (int i = 0; i < 4; i++)
        #pragma unroll
        for (int j = 0; j < 4; j++) s[i][j] += qv[i] * kv[j];
    }
    // ---- per-row tile max (reduce over 16 tm lanes) ----
    float tmax[4];
    #pragma unroll
    for (int i = 0; i < 4; i++) {
      float m_ = fmaxf(fmaxf(s[i][0], s[i][1]), fmaxf(s[i][2], s[i][3]));
      #pragma unroll
      for (int ofs = 8; ofs >= 1; ofs >>= 1)
        m_ = fmaxf(m_, __shfl_xor_sync(0xffffffffu, m_, ofs));
      tmax[i] = m_;
    }
    if (tm == 0) {
      #pragma unroll
      for (int i = 0; i < 4; i++) {
        int n = tn * 4 + i;
        float old = row_max[n];
        float nm = fmaxf(old, tmax[i]);
        float corr = __expf(old - nm);
        row_max[n] = nm;
        row_corr[n] = corr;
        row_sum[n] *= corr;
      }
    }
    __syncthreads();   // S-phase reads of kp_s done; row stats visible
    // ---- P = exp(S - max), stash in kp_s as [n][m]; accumulate row sums ----
    #pragma unroll
    for (int i = 0; i < 4; i++) {
      int n = tn * 4 + i;
      float nm = row_max[n];
      float psum = 0.f;
      #pragma unroll
      for (int j = 0; j < 4; j++) {
        float p = __expf(s[i][j] - nm);
        kp_s[n * 65 + tm * 4 + j] = p;
        psum += p;
      }
      #pragma unroll
      for (int ofs = 8; ofs >= 1; ofs >>= 1)
        psum += __shfl_xor_sync(0xffffffffu, psum, ofs);
      if (tm == 0) row_sum[n] += psum;
    }
    __syncthreads();   // p visible
    // ---- O rescale + AV (thread = 4 rows x 4 channels, c0 = tm*4) ----
    #pragma unroll
    for (int i = 0; i < 4; i++) {
      float corr = row_corr[tn * 4 + i];
      #pragma unroll
      for (int j = 0; j < 4; j++) o_acc[i][j] *= corr;
    }
    #pragma unroll 8
    for (int m = 0; m < 64; m++) {
      float pv[4], vv[4];
      #pragma unroll
      for (int i = 0; i < 4; i++) pv[i] = kp_s[(tn * 4 + i) * 65 + m];
      #pragma unroll
      for (int j = 0; j < 4; j++) vv[j] = v_s[m * 65 + tm * 4 + j];
      #pragma unroll
      for (int i = 0; i < 4; i++)
        #pragma unroll
        for (int j = 0; j < 4; j++) o_acc[i][j] += pv[i] * vv[j];
    }
    __syncthreads();   // before next tile overwrites kp_s / v_s
  }
  const float* xqg = A.xq[u];
  float* og = A.out[u];
  #pragma unroll
  for (int i = 0; i < 4; i++) {
    int n = n0 + tn * 4 + i;
    float inv = 1.f / row_sum[tn * 4 + i];
    #pragma unroll
    for (int j = 0; j < 4; j++) {
      int c = tm * 4 + j;
      og[c * HW + n] = o_acc[i][j] * inv + xqg[c * HW + n];
    }
  }
}

// ---------------- host orchestration ----------------
extern "C" void kernel_launch(void* const* d_in, const int* in_sizes, int n_in,
                              void* d_out, int out_size) {
  const float* x1_seq = (const float*)d_in[0];
  const float* x2_seq = (const float*)d_in[1];
  const float* cw[2][2]; const float* cb[2][2];
  cw[0][0] = (const float*)d_in[2]; cb[0][0] = (const float*)d_in[3];
  cw[0][1] = (const float*)d_in[4]; cb[0][1] = (const float*)d_in[5];
  cw[1][0] = (const float*)d_in[6]; cb[1][0] = (const float*)d_in[7];
  cw[1][1] = (const float*)d_in[8]; cb[1][1] = (const float*)d_in[9];
  const float* sah_w = (const float*)d_in[10]; const float* sah_b = (const float*)d_in[11];
  const float* sac_w = (const float*)d_in[12]; const float* sac_b = (const float*)d_in[13];
  const float* cah_w = (const float*)d_in[14]; const float* cah_b = (const float*)d_in[15];
  const float* cac_w = (const float*)d_in[16]; const float* cac_b = (const float*)d_in[17];
  const float* dec_w1 = (const float*)d_in[18]; const float* dec_b1 = (const float*)d_in[19];
  const float* dec_w2 = (const float*)d_in[20]; const float* dec_b2 = (const float*)d_in[21];
  float* out = (float*)d_out;

  float* base = nullptr;
  cudaGetSymbolAddress((void**)&base, SCRATCH);

  const int SZ_SL = 131072;  // [2 batch][64][1024]
  float* Sh  = base;                 // 4*SZ_SL
  float* Sc  = base + 4 * SZ_SL;     // 4*SZ_SL
  float* G   = base + 8 * SZ_SL;     // 2*524288
  float* HA  = G  + 2 * 524288;
  float* CA  = HA + 262144;
  float* HB  = CA + 262144;
  float* CB  = HB + 262144;
  float* Qb  = CB + 262144;          // 8*65536
  float* Kb  = Qb + 524288;
  float* Vb  = Kb + 524288;
  float* DEC = Vb + 524288;          // 4*65536

  cudaFuncSetAttribute(flash_kernel, cudaFuncAttributeMaxDynamicSharedMemorySize, 50688);

  // zero initial state (Sh + Sc)
  zero_kernel<<<(8 * SZ_SL + 255) / 256, 256>>>(base, 8 * SZ_SL);

  auto Shp = [&](int s, int l) { return Sh + (s * 2 + l) * SZ_SL; };
  auto Scp = [&](int s, int l) { return Sc + (s * 2 + l) * SZ_SL; };

  auto step = [&](const float* x1b0, const float* x1b1,
                  const float* x2b0, const float* x2b1) {
    const float* xin[2][2] = {{x1b0, x1b1}, {x2b0, x2b1}};
    for (int l = 0; l < 2; l++) {
      int cx = (l == 0) ? 1 : 64;
      // gate conv (4 units: stream x batch)
      ConvArgs ca;
      for (int u = 0; u < 4; u++) {
        int s = u >> 1, b = u & 1;
        ca.x[u] = (l == 0) ? xin[s][b] : (Shp(s, 0) + b * 65536);
        ca.h[u] = Shp(s, l) + b * 65536;
        ca.w[u] = cw[s][l]; ca.b[u] = cb[s][l];
        ca.out[u] = G + s * 524288 + b * 262144;
      }
      ca.cx = cx; ca.chh = 64; ca.cout = 256; ca.relu = 0;
      conv3x3_kernel<<<dim3(32, 4), 256>>>(ca);
      // LSTM pointwise
      LstmArgs la;
      for (int u = 0; u < 4; u++) {
        int s = u >> 1, b = u & 1;
        la.g[u]    = G + s * 524288 + b * 262144;
        la.cold[u] = Scp(s, l) + b * 65536;
        la.hn[u]   = HA + s * 131072 + b * 65536;
        la.cn[u]   = CA + s * 131072 + b * 65536;
      }
      lstm_kernel<<<dim3(256, 4), 256>>>(la);
      // ---- self attention group (8 units) ----
      QKVArgs qa; FlashArgs fa;
      for (int a = 0; a < 4; a++) {
        int s = a >> 1; int isC = a & 1;
        const float* src = (isC ? CA : HA) + s * 131072;
        float* dst       = (isC ? CB : HB) + s * 131072;
        const float* w  = isC ? (sac_w + l * 12288) : (sah_w + l * 12288);
        const float* bb = isC ? (sac_b + l * 192)   : (sah_b + l * 192);
        for (int b = 0; b < 2; b++) {
          int uu = a * 2 + b;
          qa.xq[uu] = src + b * 65536; qa.xkv[uu] = src + b * 65536;
          qa.w[uu] = w; qa.b[uu] = bb;
          qa.q[uu] = Qb + uu * 65536; qa.k[uu] = Kb + uu * 65536; qa.v[uu] = Vb + uu * 65536;
          fa.q[uu] = qa.q[uu]; fa.k[uu] = qa.k[uu]; fa.v[uu] = qa.v[uu];
          fa.xq[uu] = src + b * 65536; fa.out[uu] = dst + b * 65536;
        }
      }
      qkv_kernel<<<dim3(4, 6, 8), 128>>>(qa);
      flash_kernel<<<dim3(16, 8), 256, 50688>>>(fa);
      // ---- cross attention group (8 units) ----
      for (int a = 0; a < 4; a++) {
        int s = a >> 1; int isC = a & 1;
        int so = 1 - s;
        const float* srcq = (isC ? CB : HB) + s  * 131072;
        const float* srck = (isC ? CB : HB) + so * 131072;
        float* dst = isC ? Scp(s, l) : Shp(s, l);
        const float* w  = isC ? (cac_w + l * 12288) : (cah_w + l * 12288);
        const float* bb = isC ? (cac_b + l * 192)   : (cah_b + l * 192);
        for (int b = 0; b < 2; b++) {
          int uu = a * 2 + b;
          qa.xq[uu] = srcq + b * 65536; qa.xkv[uu] = srck + b * 65536;
          qa.w[uu] = w; qa.b[uu] = bb;
          fa.xq[uu] = srcq + b * 65536; fa.out[uu] = dst + b * 65536;
        }
      }
      qkv_kernel<<<dim3(4, 6, 8), 128>>>(qa);
      flash_kernel<<<dim3(16, 8), 256, 50688>>>(fa);
    }
  };

  auto decode = [&](float* o1b0, float* o1b1, float* o2b0, float* o2b1) {
    ConvArgs c1;
    for (int u = 0; u < 4; u++) {
      int s = u >> 1, b = u & 1;
      c1.x[u] = Shp(s, 1) + b * 65536;
      c1.h[u] = nullptr;
      c1.w[u] = dec_w1; c1.b[u] = dec_b1;
      c1.out[u] = DEC + u * 65536;
    }
    c1.cx = 64; c1.chh = 0; c1.cout = 64; c1.relu = 1;
    conv3x3_kernel<<<dim3(8, 4), 256>>>(c1);
    ConvArgs c2;
    float* outs[4] = {o1b0, o1b1, o2b0, o2b1};
    for (int u = 0; u < 4; u++) {
      c2.x[u] = DEC + u * 65536;
      c2.h[u] = nullptr;
      c2.w[u] = dec_w2; c2.b[u] = dec_b2;
      c2.out[u] = outs[u];
    }
    c2.cx = 64; c2.chh = 0; c2.cout = 1; c2.relu = 0;
    conv3x3_kernel<<<dim3(1, 4), 256>>>(c2);
  };

  // output offsets (floats):
  // preds1: 0       [2][4][1024]
  // preds2: 8192    [2][4][1024]
  // warm1:  16384   [2][2][1024]
  // warm2:  20480   [2][2][1024]

  // warm steps
  for (int tt = 0; tt < 3; tt++) {
    const float* x1b0 = x1_seq + (0 * 3 + tt) * 1024;
    const float* x1b1 = x1_seq + (1 * 3 + tt) * 1024;
    const float* x2b0 = x2_seq + (0 * 3 + tt) * 1024;
    const float* x2b1 = x2_seq + (1 * 3 + tt) * 1024;
    step(x1b0, x1b1, x2b0, x2b1);
    if (tt < 2) {
      decode(out + 16384 + 0 * 2048 + tt * 1024,
             out + 16384 + 1 * 2048 + tt * 1024,
             out + 20480 + 0 * 2048 + tt * 1024,
             out + 20480 + 1 * 2048 + tt * 1024);
    }
  }
  // future steps (future_steps = 4 fixed by setup_inputs; last step's state unused -> skipped)
  for (int i = 0; i < 4; i++) {
    float* p1b0 = out + 0 * 4096 + i * 1024;
    float* p1b1 = out + 1 * 4096 + i * 1024;
    float* p2b0 = out + 8192 + 0 * 4096 + i * 1024;
    float* p2b1 = out + 8192 + 1 * 4096 + i * 1024;
    decode(p1b0, p1b1, p2b0, p2b1);
    if (i < 3) step(p1b0, p1b1, p2b0, p2b1);
  }
}

// round 15
// speedup vs baseline: 1.0013x; 1.0013x over previous
#include <cuda_runtime.h>
#include <math.h>

#define HW 1024

// ---------------- scratch ----------------
// layout (float offsets):
// Sh: 4 * 131072      (state h per stream,layer: [2 batch][64][1024])
// Sc: 4 * 131072
// G : 2 * 524288      (gates per stream: [2 batch][256][1024])
// HA/CA/HB/CB: each 2 * 131072
// Q/K/V: each 8 * 65536
// DEC: 4 * 65536
__device__ float SCRATCH[4980736];

// ---------------- arg structs ----------------
struct ConvArgs {
  const float* x[4]; const float* h[4];
  const float* w[4]; const float* b[4];
  float* out[4];
  int cx, chh, cout, relu;
};
struct LstmArgs {
  const float* g[4]; const float* cold[4];
  float* hn[4]; float* cn[4];
};
struct QKVArgs {
  const float* xq[8]; const float* xkv[8];
  const float* w[8];  const float* b[8];
  float* q[8]; float* k[8]; float* v[8];
};
struct FlashArgs {
  const float* q[8]; const float* k[8]; const float* v[8];
  const float* xq[8]; float* out[8];
};

// ---------------- zero ----------------
__global__ void zero_kernel(float* p, int n) {
  int i = blockIdx.x * 256 + threadIdx.x;
  if (i < n) p[i] = 0.f;
}

// ---------------- 3x3 conv (SAME, stride 1), 8 out-ch per block ----------------
__global__ __launch_bounds__(256) void conv3x3_kernel(ConvArgs A) {
  int u  = blockIdx.y;
  int ob = blockIdx.x * 8;
  int t  = threadIdx.x;
  int tx = t & 31, ty = t >> 5;
  __shared__ float plane[34 * 36];
  __shared__ float wsm[8 * 9];
  for (int i = t; i < 34 * 36; i += 256) plane[i] = 0.f;  // border stays 0 (SAME pad)
  int ctot = A.cx + A.chh;
  int nco = A.cout - ob; if (nco > 8) nco = 8;
  float acc[8][4];
  #pragma unroll
  for (int j = 0; j < 8; j++)
    #pragma unroll
    for (int k = 0; k < 4; k++) acc[j][k] = 0.f;
  const float* xp = A.x[u];
  const float* hp = A.h[u];
  const float* wp = A.w[u];
  __syncthreads();
  for (int ci = 0; ci < ctot; ci++) {
    const float* src = (ci < A.cx) ? (xp + ci * HW) : (hp + (ci - A.cx) * HW);
    #pragma unroll
    for (int k = 0; k < 4; k++) {
      int idx = t + k * 256;
      int y = idx >> 5, xx = idx & 31;
      plane[(y + 1) * 36 + (xx + 1)] = src[idx];
    }
    if (t < 72) {
      int j = t / 9, t9 = t % 9;
      wsm[t] = (j < nco) ? wp[(ob + j) * ctot * 9 + ci * 9 + t9] : 0.f;
    }
    __syncthreads();
    #pragma unroll
    for (int k = 0; k < 4; k++) {
      int y = ty + k * 8;
      float pv[9];
      #pragma unroll
      for (int dy = 0; dy < 3; dy++)
        #pragma unroll
        for (int dx = 0; dx < 3; dx++)
          pv[dy * 3 + dx] = plane[(y + dy) * 36 + tx + dx];
      #pragma unroll
      for (int j = 0; j < 8; j++) {
        float a = acc[j][k];
        #pragma unroll
        for (int q = 0; q < 9; q++) a += wsm[j * 9 + q] * pv[q];
        acc[j][k] = a;
      }
    }
    __syncthreads();
  }
  float* op = A.out[u];
  const float* bp = A.b[u];
  for (int j = 0; j < nco; j++) {
    float bias = bp[ob + j];
    #pragma unroll
    for (int k = 0; k < 4; k++) {
      float v = acc[j][k] + bias;
      if (A.relu) v = fmaxf(v, 0.f);
      op[(ob + j) * HW + (ty + k * 8) * 32 + tx] = v;
    }
  }
}

// ---------------- LSTM pointwise ----------------
__global__ __launch_bounds__(256) void lstm_kernel(LstmArgs A) {
  int u = blockIdx.y;
  int e = blockIdx.x * 256 + threadIdx.x;   // 0..65535
  int ch = e >> 10, hw = e & 1023;
  const float* g = A.g[u];
  float gi = g[ch * HW + hw];
  float gf = g[(64 + ch) * HW + hw];
  float go = g[(128 + ch) * HW + hw];
  float gg = g[(192 + ch) * HW + hw];
  float i = 1.f / (1.f + __expf(-gi));
  float f = 1.f / (1.f + __expf(-gf));
  float o = 1.f / (1.f + __expf(-go));
  float gt = tanhf(gg);
  float c = f * A.cold[u][e] + i * gt;
  A.cn[u][e] = c;
  A.hn[u][e] = o * tanhf(c);
}

// ---------------- QKV 1x1 projections (64x64 GEMM over 1024 tokens) ----------------
// grid: (4 hw-tiles of 256, 6 = {q,k,v} x {half}, 8 units), block 128
__global__ __launch_bounds__(128) void qkv_kernel(QKVArgs A) {
  int u = blockIdx.z;
  int s  = blockIdx.y >> 1;   // 0=q 1=k 2=v
  int oh = blockIdx.y & 1;    // output-channel half
  int hw0 = blockIdx.x * 256 + threadIdx.x;
  __shared__ float wsm[32 * 64];
  __shared__ float bsm[32];
  const float* wp = A.w[u] + s * 4096 + oh * 32 * 64;
  for (int i = threadIdx.x; i < 2048; i += 128) wsm[i] = wp[i];
  if (threadIdx.x < 32) bsm[threadIdx.x] = A.b[u][s * 64 + oh * 32 + threadIdx.x];
  const float* x = (s == 0) ? A.xq[u] : A.xkv[u];
  __syncthreads();
  float a0[32], a1[32];
  #pragma unroll
  for (int o = 0; o < 32; o++) { a0[o] = bsm[o]; a1[o] = bsm[o]; }
  #pragma unroll 4
  for (int c = 0; c < 64; c++) {
    float x0 = x[c * HW + hw0];
    float x1 = x[c * HW + hw0 + 128];
    #pragma unroll
    for (int o = 0; o < 32; o++) {
      float w = wsm[o * 64 + c];
      a0[o] += w * x0; a1[o] += w * x1;
    }
  }
  float* out = (s == 0) ? A.q[u] : ((s == 1) ? A.k[u] : A.v[u]);
  #pragma unroll
  for (int o = 0; o < 32; o++) {
    out[(oh * 32 + o) * HW + hw0]       = a0[o];
    out[(oh * 32 + o) * HW + hw0 + 128] = a1[o];
  }
}

// ---------------- flash attention (64 q-rows/block, 64-m tiles, online softmax) ----------------
// grid (16 n-tiles, 8 units), block 256, dynamic smem 50688 B
__global__ __launch_bounds__(256) void flash_kernel(FlashArgs A) {
  extern __shared__ float sm[];
  float* q_s  = sm;                // [n][c] stride 65
  float* kp_s = sm + 64 * 65;      // k: [c][m] stride 65 ; then p: [n][m]
  float* v_s  = sm + 2 * 64 * 65;  // [m][c] stride 65
  float* row_max  = sm + 3 * 64 * 65;
  float* row_sum  = row_max + 64;
  float* row_corr = row_sum + 64;
  int u  = blockIdx.y;
  int n0 = blockIdx.x * 64;
  int t  = threadIdx.x;
  int tn = t >> 4, tm = t & 15;
  const float* qg = A.q[u];
  const float* kg = A.k[u];
  const float* vg = A.v[u];
  #pragma unroll
  for (int i = 0; i < 16; i++) {
    int e = t + i * 256;
    int n = e & 63, c = e >> 6;
    q_s[n * 65 + c] = qg[c * HW + n0 + n] * 0.125f;  // fold 1/sqrt(64)
  }
  if (t < 64) { row_max[t] = -3.0e38f; row_sum[t] = 0.f; }
  float o_acc[4][4];
  #pragma unroll
  for (int i = 0; i < 4; i++)
    #pragma unroll
    for (int j = 0; j < 4; j++) o_acc[i][j] = 0.f;
  __syncthreads();

  for (int mt = 0; mt < 16; mt++) {
    int m0 = mt * 64;
    #pragma unroll
    for (int i = 0; i < 16; i++) {
      int e = t + i * 256;
      int m = e & 63, c = e >> 6;
      kp_s[c * 65 + m] = kg[c * HW + m0 + m];
      v_s [m * 65 + c] = vg[c * HW + m0 + m];
    }
    __syncthreads();
    // ---- S tile (4x4 per thread) ----
    float s[4][4];
    #pragma unroll
    for (int i = 0; i < 4; i++)
      #pragma unroll
      for (int j = 0; j < 4; j++) s[i][j] = 0.f;
    #pragma unroll 8
    for (int c = 0; c < 64; c++) {
      float qv[4], kv[4];
      #pragma unroll
      for (int i = 0; i < 4; i++) qv[i] = q_s[(tn * 4 + i) * 65 + c];
      #pragma unroll
      for (int j = 0; j < 4; j++) kv[j] = kp_s[c * 65 + tm * 4 + j];
      #pragma unroll
      for (int i = 0; i < 4; i++)
        #pragma unroll
        for (int j = 0; j < 4; j++) s[i][j] += qv[i] * kv[j];
    }
    // ---- per-row tile max (reduce over 16 tm lanes) ----
    float tmax[4];
    #pragma unroll
    for (int i = 0; i < 4; i++) {
      float m_ = fmaxf(fmaxf(s[i][0], s[i][1]), fmaxf(s[i][2], s[i][3]));
      #pragma unroll
      for (int ofs = 8; ofs >= 1; ofs >>= 1)
        m_ = fmaxf(m_, __shfl_xor_sync(0xffffffffu, m_, ofs));
      tmax[i] = m_;
    }
    if (tm == 0) {
      #pragma unroll
      for (int i = 0; i < 4; i++) {
        int n = tn * 4 + i;
        float old = row_max[n];
        float nm = fmaxf(old, tmax[i]);
        float corr = __expf(old - nm);
        row_max[n] = nm;
        row_corr[n] = corr;
        row_sum[n] *= corr;
      }
    }
    __syncthreads();   // S-phase reads of kp_s done; row stats visible
    // ---- P = exp(S - max), stash in kp_s as [n][m]; accumulate row sums ----
    #pragma unroll
    for (int i = 0; i < 4; i++) {
      int n = tn * 4 + i;
      float nm = row_max[n];
      float psum = 0.f;
      #pragma unroll
      for (int j = 0; j < 4; j++) {
        float p = __expf(s[i][j] - nm);
        kp_s[n * 65 + tm * 4 + j] = p;
        psum += p;
      }
      #pragma unroll
      for (int ofs = 8; ofs >= 1; ofs >>= 1)
        psum += __shfl_xor_sync(0xffffffffu, psum, ofs);
      if (tm == 0) row_sum[n] += psum;
    }
    __syncthreads();   // p visible
    // ---- O rescale + AV (thread = 4 rows x 4 channels, c0 = tm*4) ----
    #pragma unroll
    for (int i = 0; i < 4; i++) {
      float corr = row_corr[tn * 4 + i];
      #pragma unroll
      for (int j = 0; j < 4; j++) o_acc[i][j] *= corr;
    }
    #pragma unroll 8
    for (int m = 0; m < 64; m++) {
      float pv[4], vv[4];
      #pragma unroll
      for (int i = 0; i < 4; i++) pv[i] = kp_s[(tn * 4 + i) * 65 + m];
      #pragma unroll
      for (int j = 0; j < 4; j++) vv[j] = v_s[m * 65 + tm * 4 + j];
      #pragma unroll
      for (int i = 0; i < 4; i++)
        #pragma unroll
        for (int j = 0; j < 4; j++) o_acc[i][j] += pv[i] * vv[j];
    }
    __syncthreads();   // before next tile overwrites kp_s / v_s
  }
  const float* xqg = A.xq[u];
  float* og = A.out[u];
  #pragma unroll
  for (int i = 0; i < 4; i++) {
    int n = n0 + tn * 4 + i;
    float inv = 1.f / row_sum[tn * 4 + i];
    #pragma unroll
    for (int j = 0; j < 4; j++) {
      int c = tm * 4 + j;
      og[c * HW + n] = o_acc[i][j] * inv + xqg[c * HW + n];
    }
  }
}

// ---------------- host orchestration ----------------
extern "C" void kernel_launch(void* const* d_in, const int* in_sizes, int n_in,
                              void* d_out, int out_size) {
  const float* x1_seq = (const float*)d_in[0];
  const float* x2_seq = (const float*)d_in[1];
  const float* cw[2][2]; const float* cb[2][2];
  cw[0][0] = (const float*)d_in[2]; cb[0][0] = (const float*)d_in[3];
  cw[0][1] = (const float*)d_in[4]; cb[0][1] = (const float*)d_in[5];
  cw[1][0] = (const float*)d_in[6]; cb[1][0] = (const float*)d_in[7];
  cw[1][1] = (const float*)d_in[8]; cb[1][1] = (const float*)d_in[9];
  const float* sah_w = (const float*)d_in[10]; const float* sah_b = (const float*)d_in[11];
  const float* sac_w = (const float*)d_in[12]; const float* sac_b = (const float*)d_in[13];
  const float* cah_w = (const float*)d_in[14]; const float* cah_b = (const float*)d_in[15];
  const float* cac_w = (const float*)d_in[16]; const float* cac_b = (const float*)d_in[17];
  const float* dec_w1 = (const float*)d_in[18]; const float* dec_b1 = (const float*)d_in[19];
  const float* dec_w2 = (const float*)d_in[20]; const float* dec_b2 = (const float*)d_in[21];
  float* out = (float*)d_out;

  float* base = nullptr;
  cudaGetSymbolAddress((void**)&base, SCRATCH);

  const int SZ_SL = 131072;  // [2 batch][64][1024]
  float* Sh  = base;                 // 4*SZ_SL
  float* Sc  = base + 4 * SZ_SL;     // 4*SZ_SL
  float* G   = base + 8 * SZ_SL;     // 2*524288
  float* HA  = G  + 2 * 524288;
  float* CA  = HA + 262144;
  float* HB  = CA + 262144;
  float* CB  = HB + 262144;
  float* Qb  = CB + 262144;          // 8*65536
  float* Kb  = Qb + 524288;
  float* Vb  = Kb + 524288;
  float* DEC = Vb + 524288;          // 4*65536

  cudaFuncSetAttribute(flash_kernel, cudaFuncAttributeMaxDynamicSharedMemorySize, 50688);

  // zero initial state (Sh + Sc)
  zero_kernel<<<(8 * SZ_SL + 255) / 256, 256>>>(base, 8 * SZ_SL);

  auto Shp = [&](int s, int l) { return Sh + (s * 2 + l) * SZ_SL; };
  auto Scp = [&](int s, int l) { return Sc + (s * 2 + l) * SZ_SL; };

  auto step = [&](const float* x1b0, const float* x1b1,
                  const float* x2b0, const float* x2b1) {
    const float* xin[2][2] = {{x1b0, x1b1}, {x2b0, x2b1}};
    for (int l = 0; l < 2; l++) {
      int cx = (l == 0) ? 1 : 64;
      // gate conv (4 units: stream x batch)
      ConvArgs ca;
      for (int u = 0; u < 4; u++) {
        int s = u >> 1, b = u & 1;
        ca.x[u] = (l == 0) ? xin[s][b] : (Shp(s, 0) + b * 65536);
        ca.h[u] = Shp(s, l) + b * 65536;
        ca.w[u] = cw[s][l]; ca.b[u] = cb[s][l];
        ca.out[u] = G + s * 524288 + b * 262144;
      }
      ca.cx = cx; ca.chh = 64; ca.cout = 256; ca.relu = 0;
      conv3x3_kernel<<<dim3(32, 4), 256>>>(ca);
      // LSTM pointwise
      LstmArgs la;
      for (int u = 0; u < 4; u++) {
        int s = u >> 1, b = u & 1;
        la.g[u]    = G + s * 524288 + b * 262144;
        la.cold[u] = Scp(s, l) + b * 65536;
        la.hn[u]   = HA + s * 131072 + b * 65536;
        la.cn[u]   = CA + s * 131072 + b * 65536;
      }
      lstm_kernel<<<dim3(256, 4), 256>>>(la);
      // ---- self attention group (8 units) ----
      QKVArgs qa; FlashArgs fa;
      for (int a = 0; a < 4; a++) {
        int s = a >> 1; int isC = a & 1;
        const float* src = (isC ? CA : HA) + s * 131072;
        float* dst       = (isC ? CB : HB) + s * 131072;
        const float* w  = isC ? (sac_w + l * 12288) : (sah_w + l * 12288);
        const float* bb = isC ? (sac_b + l * 192)   : (sah_b + l * 192);
        for (int b = 0; b < 2; b++) {
          int uu = a * 2 + b;
          qa.xq[uu] = src + b * 65536; qa.xkv[uu] = src + b * 65536;
          qa.w[uu] = w; qa.b[uu] = bb;
          qa.q[uu] = Qb + uu * 65536; qa.k[uu] = Kb + uu * 65536; qa.v[uu] = Vb + uu * 65536;
          fa.q[uu] = qa.q[uu]; fa.k[uu] = qa.k[uu]; fa.v[uu] = qa.v[uu];
          fa.xq[uu] = src + b * 65536; fa.out[uu] = dst + b * 65536;
        }
      }
      qkv_kernel<<<dim3(4, 6, 8), 128>>>(qa);
      flash_kernel<<<dim3(16, 8), 256, 50688>>>(fa);
      // ---- cross attention group (8 units) ----
      for (int a = 0; a < 4; a++) {
        int s = a >> 1; int isC = a & 1;
        int so = 1 - s;
        const float* srcq = (isC ? CB : HB) + s  * 131072;
        const float* srck = (isC ? CB : HB) + so * 131072;
        float* dst = isC ? Scp(s, l) : Shp(s, l);
        const float* w  = isC ? (cac_w + l * 12288) : (cah_w + l * 12288);
        const float* bb = isC ? (cac_b + l * 192)   : (cah_b + l * 192);
        for (int b = 0; b < 2; b++) {
          int uu = a * 2 + b;
          qa.xq[uu] = srcq + b * 65536; qa.xkv[uu] = srck + b * 65536;
          qa.w[uu] = w; qa.b[uu] = bb;
          fa.xq[uu] = srcq + b * 65536; fa.out[uu] = dst + b * 65536;
        }
      }
      qkv_kernel<<<dim3(4, 6, 8), 128>>>(qa);
      flash_kernel<<<dim3(16, 8), 256, 50688>>>(fa);
    }
  };

  auto decode = [&](float* o1b0, float* o1b1, float* o2b0, float* o2b1) {
    ConvArgs c1;
    for (int u = 0; u < 4; u++) {
      int s = u >> 1, b = u & 1;
      c1.x[u] = Shp(s, 1) + b * 65536;
      c1.h[u] = nullptr;
      c1.w[u] = dec_w1; c1.b[u] = dec_b1;
      c1.out[u] = DEC + u * 65536;
    }
    c1.cx = 64; c1.chh = 0; c1.cout = 64; c1.relu = 1;
    conv3x3_kernel<<<dim3(8, 4), 256>>>(c1);
    ConvArgs c2;
    float* outs[4] = {o1b0, o1b1, o2b0, o2b1};
    for (int u = 0; u < 4; u++) {
      c2.x[u] = DEC + u * 65536;
      c2.h[u] = nullptr;
      c2.w[u] = dec_w2; c2.b[u] = dec_b2;
      c2.out[u] = outs[u];
    }
    c2.cx = 64; c2.chh = 0; c2.cout = 1; c2.relu = 0;
    conv3x3_kernel<<<dim3(1, 4), 256>>>(c2);
  };

  // output offsets (floats):
  // preds1: 0       [2][4][1024]
  // preds2: 8192    [2][4][1024]
  // warm1:  16384   [2][2][1024]
  // warm2:  20480   [2][2][1024]

  // warm steps
  for (int tt = 0; tt < 3; tt++) {
    const float* x1b0 = x1_seq + (0 * 3 + tt) * 1024;
    const float* x1b1 = x1_seq + (1 * 3 + tt) * 1024;
    const float* x2b0 = x2_seq + (0 * 3 + tt) * 1024;
    const float* x2b1 = x2_seq + (1 * 3 + tt) * 1024;
    step(x1b0, x1b1, x2b0, x2b1);
    if (tt < 2) {
      decode(out + 16384 + 0 * 2048 + tt * 1024,
             out + 16384 + 1 * 2048 + tt * 1024,
             out + 20480 + 0 * 2048 + tt * 1024,
             out + 20480 + 1 * 2048 + tt * 1024);
    }
  }
  // future steps (future_steps = 4 fixed by setup_inputs; last step's state unused -> skipped)
  for (int i = 0; i < 4; i++) {
    float* p1b0 = out + 0 * 4096 + i * 1024;
    float* p1b1 = out + 1 * 4096 + i * 1024;
    float* p2b0 = out + 8192 + 0 * 4096 + i * 1024;
    float* p2b1 = out + 8192 + 1 * 4096 + i * 1024;
    decode(p1b0, p1b1, p2b0, p2b1);
    if (i < 3) step(p1b0, p1b1, p2b0, p2b1);
  }
}

// round 17
// speedup vs baseline: 1.3747x; 1.3729x over previous
#include <cuda_runtime.h>
#include <math.h>
#include <stdint.h>

#define HW 1024
#define FS 72   // smem stride (floats) for flash tiles: 72 mod 32 == 8 -> conflict-free frag patterns

// ---------------- scratch ----------------
__device__ float SCRATCH[4980736];

// ---------------- arg structs ----------------
struct ConvArgs {
  const float* x[4]; const float* h[4];
  const float* w[4]; const float* b[4];
  float* out[4];
  int cx, chh, cout, relu;
};
struct LstmArgs {
  const float* g[4]; const float* cold[4];
  float* hn[4]; float* cn[4];
};
struct QKVArgs {
  const float* xq[8]; const float* xkv[8];
  const float* w[8];  const float* b[8];
  float* q[8]; float* k[8]; float* v[8];
};
struct FlashArgs {
  const float* q[8]; const float* k[8]; const float* v[8];
  const float* xq[8]; float* out[8];
};

// ---------------- helpers ----------------
__device__ __forceinline__ uint32_t f2t(float x) {
  uint32_t r;
  asm("cvt.rna.tf32.f32 %0, %1;" : "=r"(r) : "f"(x));
  return r;
}
__device__ __forceinline__ void mma8(float* d, const uint32_t* a, const uint32_t* b) {
  asm volatile(
    "mma.sync.aligned.m16n8k8.row.col.f32.tf32.tf32.f32 "
    "{%0,%1,%2,%3}, {%4,%5,%6,%7}, {%8,%9}, {%0,%1,%2,%3};"
    : "+f"(d[0]), "+f"(d[1]), "+f"(d[2]), "+f"(d[3])
    : "r"(a[0]), "r"(a[1]), "r"(a[2]), "r"(a[3]), "r"(b[0]), "r"(b[1]));
}

// ---------------- zero ----------------
__global__ void zero_kernel(float* p, int n) {
  int i = blockIdx.x * 256 + threadIdx.x;
  if (i < n) p[i] = 0.f;
}

// ---------------- 3x3 conv (SAME, stride 1), 8 out-ch per block ----------------
__global__ __launch_bounds__(256) void conv3x3_kernel(ConvArgs A) {
  int u  = blockIdx.y;
  int ob = blockIdx.x * 8;
  int t  = threadIdx.x;
  int tx = t & 31, ty = t >> 5;
  __shared__ float plane[34 * 36];
  __shared__ float wsm[8 * 9];
  for (int i = t; i < 34 * 36; i += 256) plane[i] = 0.f;
  int ctot = A.cx + A.chh;
  int nco = A.cout - ob; if (nco > 8) nco = 8;
  float acc[8][4];
  #pragma unroll
  for (int j = 0; j < 8; j++)
    #pragma unroll
    for (int k = 0; k < 4; k++) acc[j][k] = 0.f;
  const float* xp = A.x[u];
  const float* hp = A.h[u];
  const float* wp = A.w[u];
  __syncthreads();
  for (int ci = 0; ci < ctot; ci++) {
    const float* src = (ci < A.cx) ? (xp + ci * HW) : (hp + (ci - A.cx) * HW);
    #pragma unroll
    for (int k = 0; k < 4; k++) {
      int idx = t + k * 256;
      int y = idx >> 5, xx = idx & 31;
      plane[(y + 1) * 36 + (xx + 1)] = src[idx];
    }
    if (t < 72) {
      int j = t / 9, t9 = t % 9;
      wsm[t] = (j < nco) ? wp[(ob + j) * ctot * 9 + ci * 9 + t9] : 0.f;
    }
    __syncthreads();
    #pragma unroll
    for (int k = 0; k < 4; k++) {
      int y = ty + k * 8;
      float pv[9];
      #pragma unroll
      for (int dy = 0; dy < 3; dy++)
        #pragma unroll
        for (int dx = 0; dx < 3; dx++)
          pv[dy * 3 + dx] = plane[(y + dy) * 36 + tx + dx];
      #pragma unroll
      for (int j = 0; j < 8; j++) {
        float a = acc[j][k];
        #pragma unroll
        for (int q = 0; q < 9; q++) a += wsm[j * 9 + q] * pv[q];
        acc[j][k] = a;
      }
    }
    __syncthreads();
  }
  float* op = A.out[u];
  const float* bp = A.b[u];
  for (int j = 0; j < nco; j++) {
    float bias = bp[ob + j];
    #pragma unroll
    for (int k = 0; k < 4; k++) {
      float v = acc[j][k] + bias;
      if (A.relu) v = fmaxf(v, 0.f);
      op[(ob + j) * HW + (ty + k * 8) * 32 + tx] = v;
    }
  }
}

// ---------------- LSTM pointwise ----------------
__global__ __launch_bounds__(256) void lstm_kernel(LstmArgs A) {
  int u = blockIdx.y;
  int e = blockIdx.x * 256 + threadIdx.x;
  int ch = e >> 10, hw = e & 1023;
  const float* g = A.g[u];
  float gi = g[ch * HW + hw];
  float gf = g[(64 + ch) * HW + hw];
  float go = g[(128 + ch) * HW + hw];
  float gg = g[(192 + ch) * HW + hw];
  float i = 1.f / (1.f + __expf(-gi));
  float f = 1.f / (1.f + __expf(-gf));
  float o = 1.f / (1.f + __expf(-go));
  float gt = tanhf(gg);
  float c = f * A.cold[u][e] + i * gt;
  A.cn[u][e] = c;
  A.hn[u][e] = o * tanhf(c);
}

// ---------------- QKV 1x1 projections ----------------
// grid: (4 token-tiles of 256, 12 = {q,k,v} x {quarter}, 8 units), block 128
__global__ __launch_bounds__(128) void qkv_kernel(QKVArgs A) {
  int u  = blockIdx.z;
  int s  = blockIdx.y >> 2;   // 0=q 1=k 2=v
  int oq = blockIdx.y & 3;    // 16-channel quarter
  int t  = threadIdx.x;
  int hw0 = blockIdx.x * 256 + t;
  __shared__ float wsm[16 * 64];
  __shared__ float bsm[16];
  const float* wp = A.w[u] + s * 4096 + oq * 16 * 64;
  for (int i = t; i < 1024; i += 128) wsm[i] = wp[i];
  if (t < 16) bsm[t] = A.b[u][s * 64 + oq * 16 + t];
  const float* x = (s == 0) ? A.xq[u] : A.xkv[u];
  __syncthreads();
  float a0[16], a1[16];
  #pragma unroll
  for (int o = 0; o < 16; o++) { a0[o] = bsm[o]; a1[o] = bsm[o]; }
  #pragma unroll 4
  for (int c = 0; c < 64; c++) {
    float x0 = x[c * HW + hw0];
    float x1 = x[c * HW + hw0 + 128];
    #pragma unroll
    for (int o = 0; o < 16; o++) {
      float w = wsm[o * 64 + c];
      a0[o] += w * x0; a1[o] += w * x1;
    }
  }
  float* out = (s == 0) ? A.q[u] : ((s == 1) ? A.k[u] : A.v[u]);
  #pragma unroll
  for (int o = 0; o < 16; o++) {
    out[(oq * 16 + o) * HW + hw0]       = a0[o];
    out[(oq * 16 + o) * HW + hw0 + 128] = a1[o];
  }
}

// ---------------- flash attention, tf32 mma ----------------
// Block: 128 threads (4 warps), 64 q-rows. S phase: warps partition n (16 rows each,
// full 64 m per warp -> softmax state in registers). AV phase computed transposed:
// O^T[c][n] = V_store[c][m] @ P^T[m][n], warps partition c. All smem stride FS=72.
// grid (16 n-tiles, 8 units), dynamic smem 74240 B
__global__ __launch_bounds__(128) void flash_kernel(FlashArgs A) {
  extern __shared__ uint32_t sm[];
  uint32_t* q_s = sm;              // [n][c]
  uint32_t* k_s = sm + 64 * FS;    // [c][m]
  uint32_t* v_s = sm + 2 * 64 * FS;// [c][m]
  uint32_t* p_s = sm + 3 * 64 * FS;// [n][m]
  float* row_corr = (float*)(sm + 4 * 64 * FS);
  float* row_sum  = row_corr + 64;

  int u = blockIdx.y, n0 = blockIdx.x * 64;
  int t = threadIdx.x;
  int w = t >> 5, lane = t & 31;
  int g = lane >> 2, tig = lane & 3;
  int nb = w * 16, cb = w * 16;

  const float* qg = A.q[u];
  const float* kg = A.k[u];
  const float* vg = A.v[u];

  // load q transposed into q_s[n][c], scale 1/sqrt(64) folded, tf32
  {
    int n4 = (t & 15) * 4;
    int c0 = t >> 4;
    #pragma unroll
    for (int j = 0; j < 8; j++) {
      int c = c0 + j * 8;
      float4 qv = *(const float4*)(qg + c * HW + n0 + n4);
      q_s[(n4 + 0) * FS + c] = f2t(qv.x * 0.125f);
      q_s[(n4 + 1) * FS + c] = f2t(qv.y * 0.125f);
      q_s[(n4 + 2) * FS + c] = f2t(qv.z * 0.125f);
      q_s[(n4 + 3) * FS + c] = f2t(qv.w * 0.125f);
    }
  }

  float o_frag[8][4];
  #pragma unroll
  for (int nt = 0; nt < 8; nt++)
    #pragma unroll
    for (int r = 0; r < 4; r++) o_frag[nt][r] = 0.f;
  float m_r0 = -3.0e38f, m_r1 = -3.0e38f;
  float l_r0 = 0.f, l_r1 = 0.f;

  __syncthreads();

  for (int mt = 0; mt < 16; mt++) {
    int m0 = mt * 64;
    // ---- load k,v tiles (tf32) ----
    {
      int m4 = (t & 15) * 4;
      int c0 = t >> 4;
      #pragma unroll
      for (int j = 0; j < 8; j++) {
        int c = c0 + j * 8;
        float4 k4 = *(const float4*)(kg + c * HW + m0 + m4);
        float4 v4 = *(const float4*)(vg + c * HW + m0 + m4);
        uint4 kk, vv;
        kk.x = f2t(k4.x); kk.y = f2t(k4.y); kk.z = f2t(k4.z); kk.w = f2t(k4.w);
        vv.x = f2t(v4.x); vv.y = f2t(v4.y); vv.z = f2t(v4.z); vv.w = f2t(v4.w);
        *(uint4*)(k_s + c * FS + m4) = kk;
        *(uint4*)(v_s + c * FS + m4) = vv;
      }
    }
    __syncthreads();

    // ---- S = Q K^T (warp owns rows nb..nb+15, all 64 m) ----
    float s_frag[8][4];
    #pragma unroll
    for (int i = 0; i < 8; i++)
      #pragma unroll
      for (int r = 0; r < 4; r++) s_frag[i][r] = 0.f;
    #pragma unroll
    for (int kc = 0; kc < 8; kc++) {
      uint32_t a[4];
      const uint32_t* qb = q_s + nb * FS + kc * 8;
      a[0] = qb[g * FS + tig];
      a[1] = qb[(g + 8) * FS + tig];
      a[2] = qb[g * FS + tig + 4];
      a[3] = qb[(g + 8) * FS + tig + 4];
      #pragma unroll
      for (int mtile = 0; mtile < 8; mtile++) {
        uint32_t b[2];
        b[0] = k_s[(kc * 8 + tig) * FS + mtile * 8 + g];
        b[1] = k_s[(kc * 8 + tig + 4) * FS + mtile * 8 + g];
        mma8(s_frag[mtile], a, b);
      }
    }

    // ---- online softmax (rows nb+g, nb+g+8; 4-lane quad shares a row) ----
    float tmax0 = -3.0e38f, tmax1 = -3.0e38f;
    #pragma unroll
    for (int i = 0; i < 8; i++) {
      tmax0 = fmaxf(tmax0, fmaxf(s_frag[i][0], s_frag[i][1]));
      tmax1 = fmaxf(tmax1, fmaxf(s_frag[i][2], s_frag[i][3]));
    }
    tmax0 = fmaxf(tmax0, __shfl_xor_sync(0xffffffffu, tmax0, 1));
    tmax0 = fmaxf(tmax0, __shfl_xor_sync(0xffffffffu, tmax0, 2));
    tmax1 = fmaxf(tmax1, __shfl_xor_sync(0xffffffffu, tmax1, 1));
    tmax1 = fmaxf(tmax1, __shfl_xor_sync(0xffffffffu, tmax1, 2));
    float mn0 = fmaxf(m_r0, tmax0), mn1 = fmaxf(m_r1, tmax1);
    float corr0 = __expf(m_r0 - mn0), corr1 = __expf(m_r1 - mn1);
    m_r0 = mn0; m_r1 = mn1;
    float ps0 = 0.f, ps1 = 0.f;
    #pragma unroll
    for (int i = 0; i < 8; i++) {
      float e0 = __expf(s_frag[i][0] - mn0);
      float e1 = __expf(s_frag[i][1] - mn0);
      float e2 = __expf(s_frag[i][2] - mn1);
      float e3 = __expf(s_frag[i][3] - mn1);
      ps0 += e0 + e1; ps1 += e2 + e3;
      p_s[(nb + g) * FS + i * 8 + 2 * tig]         = f2t(e0);
      p_s[(nb + g) * FS + i * 8 + 2 * tig + 1]     = f2t(e1);
      p_s[(nb + g + 8) * FS + i * 8 + 2 * tig]     = f2t(e2);
      p_s[(nb + g + 8) * FS + i * 8 + 2 * tig + 1] = f2t(e3);
    }
    ps0 += __shfl_xor_sync(0xffffffffu, ps0, 1);
    ps0 += __shfl_xor_sync(0xffffffffu, ps0, 2);
    ps1 += __shfl_xor_sync(0xffffffffu, ps1, 1);
    ps1 += __shfl_xor_sync(0xffffffffu, ps1, 2);
    l_r0 = l_r0 * corr0 + ps0;
    l_r1 = l_r1 * corr1 + ps1;
    if (tig == 0) { row_corr[nb + g] = corr0; row_corr[nb + g + 8] = corr1; }
    __syncthreads();

    // ---- O^T[c][n] rescale + V @ P^T (warp owns c-rows cb..cb+15) ----
    #pragma unroll
    for (int nt = 0; nt < 8; nt++) {
      float ca = row_corr[nt * 8 + 2 * tig];
      float cc = row_corr[nt * 8 + 2 * tig + 1];
      o_frag[nt][0] *= ca; o_frag[nt][1] *= cc;
      o_frag[nt][2] *= ca; o_frag[nt][3] *= cc;
    }
    #pragma unroll
    for (int mc = 0; mc < 8; mc++) {
      uint32_t a[4];
      const uint32_t* vb = v_s + cb * FS + mc * 8;
      a[0] = vb[g * FS + tig];
      a[1] = vb[(g + 8) * FS + tig];
      a[2] = vb[g * FS + tig + 4];
      a[3] = vb[(g + 8) * FS + tig + 4];
      #pragma unroll
      for (int nt = 0; nt < 8; nt++) {
        uint32_t b[2];
        b[0] = p_s[(nt * 8 + g) * FS + mc * 8 + tig];
        b[1] = p_s[(nt * 8 + g) * FS + mc * 8 + tig + 4];
        mma8(o_frag[nt], a, b);
      }
    }
    __syncthreads();
  }

  if (tig == 0) { row_sum[nb + g] = l_r0; row_sum[nb + g + 8] = l_r1; }
  __syncthreads();

  // epilogue: normalize, residual, write out (rows c = cb+g, cb+g+8)
  const float* xqg = A.xq[u];
  float* og = A.out[u];
  #pragma unroll
  for (int nt = 0; nt < 8; nt++) {
    int n = n0 + nt * 8 + 2 * tig;
    float inv0 = 1.f / row_sum[nt * 8 + 2 * tig];
    float inv1 = 1.f / row_sum[nt * 8 + 2 * tig + 1];
    int c0r = cb + g, c1r = cb + g + 8;
    float2 x0 = *(const float2*)(xqg + c0r * HW + n);
    float2 x1 = *(const float2*)(xqg + c1r * HW + n);
    float2 o0 = make_float2(o_frag[nt][0] * inv0 + x0.x, o_frag[nt][1] * inv1 + x0.y);
    float2 o1 = make_float2(o_frag[nt][2] * inv0 + x1.x, o_frag[nt][3] * inv1 + x1.y);
    *(float2*)(og + c0r * HW + n) = o0;
    *(float2*)(og + c1r * HW + n) = o1;
  }
}

// ---------------- host orchestration ----------------
extern "C" void kernel_launch(void* const* d_in, const int* in_sizes, int n_in,
                              void* d_out, int out_size) {
  const float* x1_seq = (const float*)d_in[0];
  const float* x2_seq = (const float*)d_in[1];
  const float* cw[2][2]; const float* cb[2][2];
  cw[0][0] = (const float*)d_in[2]; cb[0][0] = (const float*)d_in[3];
  cw[0][1] = (const float*)d_in[4]; cb[0][1] = (const float*)d_in[5];
  cw[1][0] = (const float*)d_in[6]; cb[1][0] = (const float*)d_in[7];
  cw[1][1] = (const float*)d_in[8]; cb[1][1] = (const float*)d_in[9];
  const float* sah_w = (const float*)d_in[10]; const float* sah_b = (const float*)d_in[11];
  const float* sac_w = (const float*)d_in[12]; const float* sac_b = (const float*)d_in[13];
  const float* cah_w = (const float*)d_in[14]; const float* cah_b = (const float*)d_in[15];
  const float* cac_w = (const float*)d_in[16]; const float* cac_b = (const float*)d_in[17];
  const float* dec_w1 = (const float*)d_in[18]; const float* dec_b1 = (const float*)d_in[19];
  const float* dec_w2 = (const float*)d_in[20]; const float* dec_b2 = (const float*)d_in[21];
  float* out = (float*)d_out;

  float* base = nullptr;
  cudaGetSymbolAddress((void**)&base, SCRATCH);

  const int SZ_SL = 131072;
  float* Sh  = base;
  float* Sc  = base + 4 * SZ_SL;
  float* G   = base + 8 * SZ_SL;
  float* HA  = G  + 2 * 524288;
  float* CA  = HA + 262144;
  float* HB  = CA + 262144;
  float* CB  = HB + 262144;
  float* Qb  = CB + 262144;
  float* Kb  = Qb + 524288;
  float* Vb  = Kb + 524288;
  float* DEC = Vb + 524288;

  const int FLASH_SMEM = 4 * 64 * FS * 4 + 512;   // 74240
  cudaFuncSetAttribute(flash_kernel, cudaFuncAttributeMaxDynamicSharedMemorySize, FLASH_SMEM);

  zero_kernel<<<(8 * SZ_SL + 255) / 256, 256>>>(base, 8 * SZ_SL);

  auto Shp = [&](int s, int l) { return Sh + (s * 2 + l) * SZ_SL; };
  auto Scp = [&](int s, int l) { return Sc + (s * 2 + l) * SZ_SL; };

  auto step = [&](const float* x1b0, const float* x1b1,
                  const float* x2b0, const float* x2b1) {
    const float* xin[2][2] = {{x1b0, x1b1}, {x2b0, x2b1}};
    for (int l = 0; l < 2; l++) {
      int cx = (l == 0) ? 1 : 64;
      ConvArgs ca;
      for (int u = 0; u < 4; u++) {
        int s = u >> 1, b = u & 1;
        ca.x[u] = (l == 0) ? xin[s][b] : (Shp(s, 0) + b * 65536);
        ca.h[u] = Shp(s, l) + b * 65536;
        ca.w[u] = cw[s][l]; ca.b[u] = cb[s][l];
        ca.out[u] = G + s * 524288 + b * 262144;
      }
      ca.cx = cx; ca.chh = 64; ca.cout = 256; ca.relu = 0;
      conv3x3_kernel<<<dim3(32, 4), 256>>>(ca);
      LstmArgs la;
      for (int u = 0; u < 4; u++) {
        int s = u >> 1, b = u & 1;
        la.g[u]    = G + s * 524288 + b * 262144;
        la.cold[u] = Scp(s, l) + b * 65536;
        la.hn[u]   = HA + s * 131072 + b * 65536;
        la.cn[u]   = CA + s * 131072 + b * 65536;
      }
      lstm_kernel<<<dim3(256, 4), 256>>>(la);
      // self attention group
      QKVArgs qa; FlashArgs fa;
      for (int a = 0; a < 4; a++) {
        int s = a >> 1; int isC = a & 1;
        const float* src = (isC ? CA : HA) + s * 131072;
        float* dst       = (isC ? CB : HB) + s * 131072;
        const float* w  = isC ? (sac_w + l * 12288) : (sah_w + l * 12288);
        const float* bb = isC ? (sac_b + l * 192)   : (sah_b + l * 192);
        for (int b = 0; b < 2; b++) {
          int uu = a * 2 + b;
          qa.xq[uu] = src + b * 65536; qa.xkv[uu] = src + b * 65536;
          qa.w[uu] = w; qa.b[uu] = bb;
          qa.q[uu] = Qb + uu * 65536; qa.k[uu] = Kb + uu * 65536; qa.v[uu] = Vb + uu * 65536;
          fa.q[uu] = qa.q[uu]; fa.k[uu] = qa.k[uu]; fa.v[uu] = qa.v[uu];
          fa.xq[uu] = src + b * 65536; fa.out[uu] = dst + b * 65536;
        }
      }
      qkv_kernel<<<dim3(4, 12, 8), 128>>>(qa);
      flash_kernel<<<dim3(16, 8), 128, FLASH_SMEM>>>(fa);
      // cross attention group
      for (int a = 0; a < 4; a++) {
        int s = a >> 1; int isC = a & 1;
        int so = 1 - s;
        const float* srcq = (isC ? CB : HB) + s  * 131072;
        const float* srck = (isC ? CB : HB) + so * 131072;
        float* dst = isC ? Scp(s, l) : Shp(s, l);
        const float* w  = isC ? (cac_w + l * 12288) : (cah_w + l * 12288);
        const float* bb = isC ? (cac_b + l * 192)   : (cah_b + l * 192);
        for (int b = 0; b < 2; b++) {
          int uu = a * 2 + b;
          qa.xq[uu] = srcq + b * 65536; qa.xkv[uu] = srck + b * 65536;
          qa.w[uu] = w; qa.b[uu] = bb;
          fa.xq[uu] = srcq + b * 65536; fa.out[uu] = dst + b * 65536;
        }
      }
      qkv_kernel<<<dim3(4, 12, 8), 128>>>(qa);
      flash_kernel<<<dim3(16, 8), 128, FLASH_SMEM>>>(fa);
    }
  };

  auto decode = [&](float* o1b0, float* o1b1, float* o2b0, float* o2b1) {
    ConvArgs c1;
    for (int u = 0; u < 4; u++) {
      int s = u >> 1, b = u & 1;
      c1.x[u] = Shp(s, 1) + b * 65536;
      c1.h[u] = nullptr;
      c1.w[u] = dec_w1; c1.b[u] = dec_b1;
      c1.out[u] = DEC + u * 65536;
    }
    c1.cx = 64; c1.chh = 0; c1.cout = 64; c1.relu = 1;
    conv3x3_kernel<<<dim3(8, 4), 256>>>(c1);
    ConvArgs c2;
    float* outs[4] = {o1b0, o1b1, o2b0, o2b1};
    for (int u = 0; u < 4; u++) {
      c2.x[u] = DEC + u * 65536;
      c2.h[u] = nullptr;
      c2.w[u] = dec_w2; c2.b[u] = dec_b2;
      c2.out[u] = outs[u];
    }
    c2.cx = 64; c2.chh = 0; c2.cout = 1; c2.relu = 0;
    conv3x3_kernel<<<dim3(1, 4), 256>>>(c2);
  };

  // warm steps
  for (int tt = 0; tt < 3; tt++) {
    const float* x1b0 = x1_seq + (0 * 3 + tt) * 1024;
    const float* x1b1 = x1_seq + (1 * 3 + tt) * 1024;
    const float* x2b0 = x2_seq + (0 * 3 + tt) * 1024;
    const float* x2b1 = x2_seq + (1 * 3 + tt) * 1024;
    step(x1b0, x1b1, x2b0, x2b1);
    if (tt < 2) {
      decode(out + 16384 + 0 * 2048 + tt * 1024,
             out + 16384 + 1 * 2048 + tt * 1024,
             out + 20480 + 0 * 2048 + tt * 1024,
             out + 20480 + 1 * 2048 + tt * 1024);
    }
  }
  // future steps (future_steps = 4; last step's state unused -> skipped)
  for (int i = 0; i < 4; i++) {
    float* p1b0 = out + 0 * 4096 + i * 1024;
    float* p1b1 = out + 1 * 4096 + i * 1024;
    float* p2b0 = out + 8192 + 0 * 4096 + i * 1024;
    float* p2b1 = out + 8192 + 1 * 4096 + i * 1024;
    decode(p1b0, p1b1, p2b0, p2b1);
    if (i < 3) step(p1b0, p1b1, p2b0, p2b1);
  }
}